// round 13
// baseline (speedup 1.0000x reference)
#include <cuda_runtime.h>
#include <cstdint>

// MaxPoolingMatching via mma.sync tf32 (base PTX; sm_103 target, no 'a' features).
//
//   num[b,l,m,p] = sum_d s1[b,l,d] * (k[p,d]^2 * s2[b,m,d])
//   out[b,l,p]   = n1inv[b,l,p] * max_m ( num * n2inv[b,m,p] )
//
// R12 -> R13: mpm reverted to the proven R7 structure (76.5us best).
// norms_kernel redesigned: thread-per-(row, 32d-chunk) with 20 p-accumulators
// in registers; only a 3-level shfl tree per p (was 5-level dependent chain
// per p -> latency bound at 14.4us). Predicted norms ~3.5us.

#define NB 16
#define NL 256
#define ND 256
#define NP 20

__device__ float g_n1inv[NB * NL * NP];
__device__ float g_n2inv[NB * NL * NP];
__device__ float g_part[2][NB * NL * NP];   // per-m-half partial maxima
__device__ float g_s1r[NB * NL * ND];       // s1 pre-rounded to tf32 (rna)

// ---------------------------------------------------------------------------
__device__ __forceinline__ uint32_t smem_u32(const void* p) {
    uint32_t a;
    asm("{ .reg .u64 t; cvta.to.shared.u64 t, %1; cvt.u32.u64 %0, t; }"
        : "=r"(a) : "l"(p));
    return a;
}
__device__ __forceinline__ uint32_t tf32r(float x) {
    uint32_t r;
    asm("cvt.rna.tf32.f32 %0, %1;" : "=r"(r) : "f"(x));
    return r;
}

#define CP16(dst, src) \
    asm volatile("cp.async.cg.shared.global [%0], [%1], 16;" \
                 :: "r"(dst), "l"(src) : "memory")
#define CP_COMMIT() asm volatile("cp.async.commit_group;" ::: "memory")
#define CP_WAIT1()  asm volatile("cp.async.wait_group 1;" ::: "memory")
#define CP_WAIT0()  asm volatile("cp.async.wait_group 0;" ::: "memory")

#define LDSM4(r0, r1, r2, r3, a) \
    asm volatile("ldmatrix.sync.aligned.m8n8.x4.shared.b16 {%0,%1,%2,%3}, [%4];" \
                 : "=r"(r0), "=r"(r1), "=r"(r2), "=r"(r3) : "r"(a))

#define MMA_TF32(d, a, b0, b1) \
    asm volatile("mma.sync.aligned.m16n8k8.row.col.f32.tf32.tf32.f32 " \
                 "{%0,%1,%2,%3}, {%4,%5,%6,%7}, {%8,%9}, {%0,%1,%2,%3};" \
                 : "+f"((d)[0]), "+f"((d)[1]), "+f"((d)[2]), "+f"((d)[3]) \
                 : "r"((a)[0]), "r"((a)[1]), "r"((a)[2]), "r"((a)[3]), \
                   "r"(b0), "r"(b1))

// ---------------------------------------------------------------------------
// Kernel 1 (redesigned): inverse norms + tf32 pre-round of s1.
// One thread per (row, 32-d chunk): 8 threads/row, 20 p-accumulators in regs,
// k^2 smem reads are warp-broadcast (8 distinct 16B addrs / warp), reduction
// is a 3-level shfl tree per p (independent chains across p).
// ---------------------------------------------------------------------------
__global__ void __launch_bounds__(256) norms_kernel(
    const float* __restrict__ s1,
    const float* __restrict__ s2,
    const float* __restrict__ kern)
{
    __shared__ float sk[NP * ND];   // k^2, 20 KB
    const int tid = threadIdx.x;
    for (int i = 0; i < 20; ++i) {
        const float v = kern[i * 256 + tid];
        sk[i * 256 + tid] = v * v;
    }
    __syncthreads();

    const int g   = blockIdx.x * 256 + tid;   // 0 .. 65535
    const int row = g >> 3;                   // 0 .. 8191
    const int ch  = g & 7;                    // 32-d chunk within row
    const int NR  = NB * NL;

    const float* src = (row < NR) ? (s1 + (size_t)row * ND)
                                  : (s2 + (size_t)(row - NR) * ND);
    float* dst = (row < NR) ? (g_n1inv + (size_t)row * NP)
                            : (g_n2inv + (size_t)(row - NR) * NP);

    // load this thread's 32 d values
    float4 v[8];
    #pragma unroll
    for (int i = 0; i < 8; ++i)
        v[i] = *reinterpret_cast<const float4*>(src + ch * 32 + i * 4);

    // fused: pre-round s1 rows to tf32 (rna) for the GEMM A operand
    if (row < NR) {
        #pragma unroll
        for (int i = 0; i < 8; ++i) {
            uint4 w;
            w.x = tf32r(v[i].x); w.y = tf32r(v[i].y);
            w.z = tf32r(v[i].z); w.w = tf32r(v[i].w);
            *reinterpret_cast<uint4*>(g_s1r + (size_t)row * ND + ch * 32 + i * 4) = w;
        }
    }

    // squares
    #pragma unroll
    for (int i = 0; i < 8; ++i) {
        v[i].x *= v[i].x; v[i].y *= v[i].y;
        v[i].z *= v[i].z; v[i].w *= v[i].w;
    }

    // 20 independent accumulators: sum_d v^2 * k^2 over this chunk
    float acc[NP];
    #pragma unroll
    for (int p = 0; p < NP; ++p) {
        const float* kp = sk + p * ND + ch * 32;
        float s = 0.f;
        #pragma unroll
        for (int i = 0; i < 8; ++i) {
            const float4 k4 = *reinterpret_cast<const float4*>(kp + i * 4);
            s = fmaf(v[i].x, k4.x, s);
            s = fmaf(v[i].y, k4.y, s);
            s = fmaf(v[i].z, k4.z, s);
            s = fmaf(v[i].w, k4.w, s);
        }
        acc[p] = s;
    }

    // reduce across the 8 chunk-threads of this row (same warp, aligned group)
    #pragma unroll
    for (int p = 0; p < NP; ++p) {
        float s = acc[p];
        s += __shfl_xor_sync(0xffffffffu, s, 1);
        s += __shfl_xor_sync(0xffffffffu, s, 2);
        s += __shfl_xor_sync(0xffffffffu, s, 4);
        acc[p] = s;
    }

    if (ch == 0) {
        #pragma unroll
        for (int p = 0; p < NP; ++p)
            dst[p] = rsqrtf(fmaxf(acc[p], 1e-12f));
    }
}

// ---------------------------------------------------------------------------
// Kernel 2: tf32 mma.sync fused GEMM + scale + max, 128x128x256 per CTA.
// (R7 structure, unmodified — best measured mainloop.)
//
// Dynamic smem (1024-aligned base):
//   [0,1024)     kw[256]   = k[p,d]^2
//   [1024,2048)  n2sm[128] = n2inv[b, m0..m0+127, p]
//   [2048,4096)  part[4][128] cross-warp row-max
//   [4096..)     3 stages x (A 16KB + B 16KB), SW128 rows of 128B
// ---------------------------------------------------------------------------
#define OFF_KW   0
#define OFF_N2   1024
#define OFF_PART 2048
#define OFF_STG  4096
#define STG_SZ   32768
#define SMEM_DYN (OFF_STG + 3 * STG_SZ + 1024)   // ~101 KB

__global__ void __launch_bounds__(256, 2)
mpm_mma_kernel(const float* __restrict__ s2,
               const float* __restrict__ kern)
{
    extern __shared__ char dynraw[];
    char* base = (char*)(((uintptr_t)dynraw + 1023) & ~(uintptr_t)1023);

    float* kwsm = (float*)(base + OFF_KW);
    float* n2sm = (float*)(base + OFF_N2);
    float* part = (float*)(base + OFF_PART);

    const int b  = blockIdx.z;
    const int p  = blockIdx.y;
    const int l0 = (blockIdx.x & 1) * 128;
    const int mh = blockIdx.x >> 1;          // m-half 0/1
    const int m0 = mh * 128;
    const int t  = threadIdx.x;
    const int lane = t & 31;
    const int warp = t >> 5;
    const int wm = warp >> 2;                // 0..1 : rows wm*64 .. +63
    const int wn = warp & 3;                 // 0..3 : cols wn*32 .. +31

    const float NEG_INF = __int_as_float(0xff800000);

    // ---- stage kw / n2 / init part ----
    {
        const float v = kern[p * ND + t];
        kwsm[t] = v * v;
        if (t < 128)
            n2sm[t] = g_n2inv[(size_t)(b * NL + m0 + t) * NP + p];
        part[t] = NEG_INF;
        part[t + 256] = NEG_INF;
    }

    // ---- staging (cp.async 16B), 8 K-chunks of 32 ----
    const int rbase = t >> 3;                // 0..31
    const int f4    = t & 7;
    const int cxor  = (f4 * 16) ^ ((rbase & 7) * 16);

    const size_t bNL = (size_t)b * NL;
    const float* Ag = g_s1r + (bNL + l0) * ND;   // pre-rounded tf32 A
    const float* Bg = s2 + (bNL + m0) * ND;

    uint32_t uA[3], uB[3];
    #pragma unroll
    for (int s = 0; s < 3; ++s) {
        uA[s] = smem_u32(base + OFF_STG + s * STG_SZ);
        uB[s] = uA[s] + 16384;
    }

    auto stage = [&](int i) {
        const int s  = i % 3;
        const int kk = i * 32;
        const uint32_t da = uA[s] + rbase * 128 + cxor;
        const uint32_t db = uB[s] + rbase * 128 + cxor;
        const float* ga = Ag + (size_t)rbase * ND + kk + f4 * 4;
        const float* gb = Bg + (size_t)rbase * ND + kk + f4 * 4;
        #pragma unroll
        for (int pp = 0; pp < 4; ++pp) {
            CP16(da + pp * 4096, ga + (size_t)pp * 32 * ND);
            CP16(db + pp * 4096, gb + (size_t)pp * 32 * ND);
        }
        CP_COMMIT();
    };

    __syncthreads();       // kw/n2/part visible before compute reads them

    stage(0);
    stage(1);

    // ---- ldmatrix per-lane addressing ----
    const int arow = ((lane >> 3) & 1) * 8 + (lane & 7);
    const int acol = ((lane >> 4) & 1) * 16;
    const int brow = ((lane >> 4) & 1) * 8 + (lane & 7);
    const int bcol = ((lane >> 3) & 1) * 16;
    const int lxor = (lane & 7) * 16;

    float acc[4][4][4];
    #pragma unroll
    for (int i = 0; i < 4; ++i)
        #pragma unroll
        for (int j = 0; j < 4; ++j)
            #pragma unroll
            for (int r = 0; r < 4; ++r) acc[i][j][r] = 0.f;

    for (int i = 0; i < 8; ++i) {
        if (i < 7) CP_WAIT1(); else CP_WAIT0();
        __syncthreads();   // publishes stage i; guarantees reads of stage i-1
                           // are done -> buffer (i+2)%3 is reusable

        const int s = i % 3;
        const uint32_t aBase = uA[s] + (wm * 64 + arow) * 128;
        const uint32_t bBase = uB[s] + (wn * 32 + brow) * 128;
        const int kk = i * 32;

        #pragma unroll
        for (int ks = 0; ks < 4; ++ks) {
            uint32_t af[4][4];
            #pragma unroll
            for (int m16 = 0; m16 < 4; ++m16)
                LDSM4(af[m16][0], af[m16][1], af[m16][2], af[m16][3],
                      aBase + m16 * 2048 + ((ks * 32 + acol) ^ lxor));

            uint32_t bf[2][4];
            #pragma unroll
            for (int pr = 0; pr < 2; ++pr)
                LDSM4(bf[pr][0], bf[pr][1], bf[pr][2], bf[pr][3],
                      bBase + pr * 2048 + ((ks * 32 + bcol) ^ lxor));

            // k^2 on B fragments + rna round (only non-MMA math in the loop)
            const float kw0 = kwsm[kk + ks * 8 + (lane & 3)];
            const float kw1 = kwsm[kk + ks * 8 + 4 + (lane & 3)];
            #pragma unroll
            for (int pr = 0; pr < 2; ++pr) {
                bf[pr][0] = tf32r(__uint_as_float(bf[pr][0]) * kw0);
                bf[pr][1] = tf32r(__uint_as_float(bf[pr][1]) * kw1);
                bf[pr][2] = tf32r(__uint_as_float(bf[pr][2]) * kw0);
                bf[pr][3] = tf32r(__uint_as_float(bf[pr][3]) * kw1);
            }

            #pragma unroll
            for (int m16 = 0; m16 < 4; ++m16)
                #pragma unroll
                for (int j = 0; j < 4; ++j)
                    MMA_TF32(acc[m16][j], af[m16],
                             bf[j >> 1][(j & 1) * 2], bf[j >> 1][(j & 1) * 2 + 1]);
        }

        if (i + 2 < 8) stage(i + 2);
    }

    // ---- epilogue: scale by n2inv, row max, cross-warp combine ----
    #pragma unroll
    for (int i = 0; i < 4; ++i) {
        float v0 = NEG_INF, v1 = NEG_INF;
        #pragma unroll
        for (int j = 0; j < 4; ++j) {
            const int nb = wn * 32 + (j >> 1) * 16 + (j & 1) * 8 + 2 * (lane & 3);
            const float sc0 = n2sm[nb], sc1 = n2sm[nb + 1];
            v0 = fmaxf(v0, fmaxf(acc[i][j][0] * sc0, acc[i][j][1] * sc1));
            v1 = fmaxf(v1, fmaxf(acc[i][j][2] * sc0, acc[i][j][3] * sc1));
        }
        v0 = fmaxf(v0, __shfl_xor_sync(0xffffffffu, v0, 1));
        v0 = fmaxf(v0, __shfl_xor_sync(0xffffffffu, v0, 2));
        v1 = fmaxf(v1, __shfl_xor_sync(0xffffffffu, v1, 1));
        v1 = fmaxf(v1, __shfl_xor_sync(0xffffffffu, v1, 2));
        if ((lane & 3) == 0) {
            const int row = wm * 64 + i * 16 + (lane >> 2);
            part[wn * 128 + row]     = fmaxf(part[wn * 128 + row], v0);
            part[wn * 128 + row + 8] = fmaxf(part[wn * 128 + row + 8], v1);
        }
    }

    __syncthreads();
    if (t < 128) {
        const float v = fmaxf(fmaxf(part[t], part[128 + t]),
                              fmaxf(part[256 + t], part[384 + t]));
        g_part[mh][(size_t)(b * NL + l0 + t) * NP + p] = v;
    }
}

// ---------------------------------------------------------------------------
// Kernel 3: combine m-half partial maxima and apply n1inv
// ---------------------------------------------------------------------------
__global__ void __launch_bounds__(256) finalize_kernel(float* __restrict__ out)
{
    const int i = blockIdx.x * 256 + threadIdx.x;   // 0 .. 81919
    out[i] = g_n1inv[i] * fmaxf(g_part[0][i], g_part[1][i]);
}

// ---------------------------------------------------------------------------
extern "C" void kernel_launch(void* const* d_in, const int* in_sizes, int n_in,
                              void* d_out, int out_size)
{
    const float* s1   = (const float*)d_in[0];  // [16,256,256]
    const float* s2   = (const float*)d_in[1];  // [16,256,256]
    const float* kern = (const float*)d_in[2];  // [20,256]
    float* out = (float*)d_out;                 // [16,256,20]

    (void)in_sizes; (void)n_in; (void)out_size;

    cudaFuncSetAttribute(mpm_mma_kernel,
                         cudaFuncAttributeMaxDynamicSharedMemorySize, SMEM_DYN);

    // norms: 8192 rows x 8 threads/row = 65536 threads
    norms_kernel<<<256, 256>>>(s1, s2, kern);

    dim3 grid(4, NP, NB);   // (l-tile x m-half, P, B) = 1280 CTAs
    mpm_mma_kernel<<<grid, 256, SMEM_DYN>>>(s2, kern);

    finalize_kernel<<<(NB * NL * NP) / 256, 256>>>(out);
}

// round 14
// speedup vs baseline: 1.5002x; 1.5002x over previous
#include <cuda_runtime.h>
#include <cstdint>

// MaxPoolingMatching via mma.sync tf32 (base PTX; sm_103 target, no 'a' features).
//
//   num[b,l,m,p] = sum_d s1[b,l,d] * (k[p,d]^2 * s2[b,m,d])
//   out[b,l,p]   = n1inv[b,l,p] * max_m ( num * n2inv[b,m,p] )
//
// R13 -> R14: norms_kernel keeps the 20-accumulator design but with an
// INTERLEAVED d-assignment (d = i*32 + ch*4): k^2 LDS becomes bank-conflict-
// free (banks ch*4..ch*4+3 cover 0-31 across the 8 ch-lanes) and global
// loads/stores become fully coalesced (8 lanes = 128B contiguous per row).
// R13's layout had ch*32 = 0 mod 32 -> 8-way conflicts on every LDS (issue
// 5.3%, 49.6us). mpm + finalize unchanged (R7 structure, best measured).

#define NB 16
#define NL 256
#define ND 256
#define NP 20

__device__ float g_n1inv[NB * NL * NP];
__device__ float g_n2inv[NB * NL * NP];
__device__ float g_part[2][NB * NL * NP];   // per-m-half partial maxima
__device__ float g_s1r[NB * NL * ND];       // s1 pre-rounded to tf32 (rna)

// ---------------------------------------------------------------------------
__device__ __forceinline__ uint32_t smem_u32(const void* p) {
    uint32_t a;
    asm("{ .reg .u64 t; cvta.to.shared.u64 t, %1; cvt.u32.u64 %0, t; }"
        : "=r"(a) : "l"(p));
    return a;
}
__device__ __forceinline__ uint32_t tf32r(float x) {
    uint32_t r;
    asm("cvt.rna.tf32.f32 %0, %1;" : "=r"(r) : "f"(x));
    return r;
}

#define CP16(dst, src) \
    asm volatile("cp.async.cg.shared.global [%0], [%1], 16;" \
                 :: "r"(dst), "l"(src) : "memory")
#define CP_COMMIT() asm volatile("cp.async.commit_group;" ::: "memory")
#define CP_WAIT1()  asm volatile("cp.async.wait_group 1;" ::: "memory")
#define CP_WAIT0()  asm volatile("cp.async.wait_group 0;" ::: "memory")

#define LDSM4(r0, r1, r2, r3, a) \
    asm volatile("ldmatrix.sync.aligned.m8n8.x4.shared.b16 {%0,%1,%2,%3}, [%4];" \
                 : "=r"(r0), "=r"(r1), "=r"(r2), "=r"(r3) : "r"(a))

#define MMA_TF32(d, a, b0, b1) \
    asm volatile("mma.sync.aligned.m16n8k8.row.col.f32.tf32.tf32.f32 " \
                 "{%0,%1,%2,%3}, {%4,%5,%6,%7}, {%8,%9}, {%0,%1,%2,%3};" \
                 : "+f"((d)[0]), "+f"((d)[1]), "+f"((d)[2]), "+f"((d)[3]) \
                 : "r"((a)[0]), "r"((a)[1]), "r"((a)[2]), "r"((a)[3]), \
                   "r"(b0), "r"(b1))

// ---------------------------------------------------------------------------
// Kernel 1: inverse norms + tf32 pre-round of s1.
// 128 threads/block, 16 rows/block (8 threads per row).
// Thread (row, ch) handles d = i*32 + ch*4, i=0..7:
//   - global float4 loads: 8 lanes/row contiguous 128B  -> coalesced
//   - k^2 LDS at p*256 + i*32 + ch*4 -> banks ch*4..+3  -> conflict-free
// 20 p-accumulators in regs; 3-level shfl tree per p across the 8 lanes.
// ---------------------------------------------------------------------------
__global__ void __launch_bounds__(128) norms_kernel(
    const float* __restrict__ s1,
    const float* __restrict__ s2,
    const float* __restrict__ kern)
{
    __shared__ float sk[NP * ND];   // k^2, 20 KB
    const int tid = threadIdx.x;
    #pragma unroll
    for (int i = 0; i < 40; ++i) {
        const float v = kern[i * 128 + tid];
        sk[i * 128 + tid] = v * v;
    }
    __syncthreads();

    const int row = blockIdx.x * 16 + (tid >> 3);   // 0 .. 8191
    const int ch  = tid & 7;
    const int NR  = NB * NL;

    const float* src = (row < NR) ? (s1 + (size_t)row * ND)
                                  : (s2 + (size_t)(row - NR) * ND);
    float* dst = (row < NR) ? (g_n1inv + (size_t)row * NP)
                            : (g_n2inv + (size_t)(row - NR) * NP);

    // load this thread's 32 d values (interleaved: d = i*32 + ch*4)
    float4 v[8];
    #pragma unroll
    for (int i = 0; i < 8; ++i)
        v[i] = *reinterpret_cast<const float4*>(src + i * 32 + ch * 4);

    // fused: pre-round s1 rows to tf32 (rna) for the GEMM A operand
    if (row < NR) {
        #pragma unroll
        for (int i = 0; i < 8; ++i) {
            uint4 w;
            w.x = tf32r(v[i].x); w.y = tf32r(v[i].y);
            w.z = tf32r(v[i].z); w.w = tf32r(v[i].w);
            *reinterpret_cast<uint4*>(g_s1r + (size_t)row * ND + i * 32 + ch * 4) = w;
        }
    }

    // squares
    #pragma unroll
    for (int i = 0; i < 8; ++i) {
        v[i].x *= v[i].x; v[i].y *= v[i].y;
        v[i].z *= v[i].z; v[i].w *= v[i].w;
    }

    // 20 independent accumulators: sum_d v^2 * k^2 over this thread's d's
    float acc[NP];
    #pragma unroll
    for (int p = 0; p < NP; ++p) {
        const float* kp = sk + p * ND + ch * 4;
        float s = 0.f;
        #pragma unroll
        for (int i = 0; i < 8; ++i) {
            const float4 k4 = *reinterpret_cast<const float4*>(kp + i * 32);
            s = fmaf(v[i].x, k4.x, s);
            s = fmaf(v[i].y, k4.y, s);
            s = fmaf(v[i].z, k4.z, s);
            s = fmaf(v[i].w, k4.w, s);
        }
        acc[p] = s;
    }

    // reduce across the 8 chunk-threads of this row (aligned 8-lane groups)
    #pragma unroll
    for (int p = 0; p < NP; ++p) {
        float s = acc[p];
        s += __shfl_xor_sync(0xffffffffu, s, 1);
        s += __shfl_xor_sync(0xffffffffu, s, 2);
        s += __shfl_xor_sync(0xffffffffu, s, 4);
        acc[p] = s;
    }

    if (ch == 0) {
        #pragma unroll
        for (int p = 0; p < NP; ++p)
            dst[p] = rsqrtf(fmaxf(acc[p], 1e-12f));
    }
}

// ---------------------------------------------------------------------------
// Kernel 2: tf32 mma.sync fused GEMM + scale + max, 128x128x256 per CTA.
// (R7 structure, unmodified — best measured mainloop.)
//
// Dynamic smem (1024-aligned base):
//   [0,1024)     kw[256]   = k[p,d]^2
//   [1024,2048)  n2sm[128] = n2inv[b, m0..m0+127, p]
//   [2048,4096)  part[4][128] cross-warp row-max
//   [4096..)     3 stages x (A 16KB + B 16KB), SW128 rows of 128B
// ---------------------------------------------------------------------------
#define OFF_KW   0
#define OFF_N2   1024
#define OFF_PART 2048
#define OFF_STG  4096
#define STG_SZ   32768
#define SMEM_DYN (OFF_STG + 3 * STG_SZ + 1024)   // ~101 KB

__global__ void __launch_bounds__(256, 2)
mpm_mma_kernel(const float* __restrict__ s2,
               const float* __restrict__ kern)
{
    extern __shared__ char dynraw[];
    char* base = (char*)(((uintptr_t)dynraw + 1023) & ~(uintptr_t)1023);

    float* kwsm = (float*)(base + OFF_KW);
    float* n2sm = (float*)(base + OFF_N2);
    float* part = (float*)(base + OFF_PART);

    const int b  = blockIdx.z;
    const int p  = blockIdx.y;
    const int l0 = (blockIdx.x & 1) * 128;
    const int mh = blockIdx.x >> 1;          // m-half 0/1
    const int m0 = mh * 128;
    const int t  = threadIdx.x;
    const int lane = t & 31;
    const int warp = t >> 5;
    const int wm = warp >> 2;                // 0..1 : rows wm*64 .. +63
    const int wn = warp & 3;                 // 0..3 : cols wn*32 .. +31

    const float NEG_INF = __int_as_float(0xff800000);

    // ---- stage kw / n2 / init part ----
    {
        const float v = kern[p * ND + t];
        kwsm[t] = v * v;
        if (t < 128)
            n2sm[t] = g_n2inv[(size_t)(b * NL + m0 + t) * NP + p];
        part[t] = NEG_INF;
        part[t + 256] = NEG_INF;
    }

    // ---- staging (cp.async 16B), 8 K-chunks of 32 ----
    const int rbase = t >> 3;                // 0..31
    const int f4    = t & 7;
    const int cxor  = (f4 * 16) ^ ((rbase & 7) * 16);

    const size_t bNL = (size_t)b * NL;
    const float* Ag = g_s1r + (bNL + l0) * ND;   // pre-rounded tf32 A
    const float* Bg = s2 + (bNL + m0) * ND;

    uint32_t uA[3], uB[3];
    #pragma unroll
    for (int s = 0; s < 3; ++s) {
        uA[s] = smem_u32(base + OFF_STG + s * STG_SZ);
        uB[s] = uA[s] + 16384;
    }

    auto stage = [&](int i) {
        const int s  = i % 3;
        const int kk = i * 32;
        const uint32_t da = uA[s] + rbase * 128 + cxor;
        const uint32_t db = uB[s] + rbase * 128 + cxor;
        const float* ga = Ag + (size_t)rbase * ND + kk + f4 * 4;
        const float* gb = Bg + (size_t)rbase * ND + kk + f4 * 4;
        #pragma unroll
        for (int pp = 0; pp < 4; ++pp) {
            CP16(da + pp * 4096, ga + (size_t)pp * 32 * ND);
            CP16(db + pp * 4096, gb + (size_t)pp * 32 * ND);
        }
        CP_COMMIT();
    };

    __syncthreads();       // kw/n2/part visible before compute reads them

    stage(0);
    stage(1);

    // ---- ldmatrix per-lane addressing ----
    const int arow = ((lane >> 3) & 1) * 8 + (lane & 7);
    const int acol = ((lane >> 4) & 1) * 16;
    const int brow = ((lane >> 4) & 1) * 8 + (lane & 7);
    const int bcol = ((lane >> 3) & 1) * 16;
    const int lxor = (lane & 7) * 16;

    float acc[4][4][4];
    #pragma unroll
    for (int i = 0; i < 4; ++i)
        #pragma unroll
        for (int j = 0; j < 4; ++j)
            #pragma unroll
            for (int r = 0; r < 4; ++r) acc[i][j][r] = 0.f;

    for (int i = 0; i < 8; ++i) {
        if (i < 7) CP_WAIT1(); else CP_WAIT0();
        __syncthreads();   // publishes stage i; guarantees reads of stage i-1
                           // are done -> buffer (i+2)%3 is reusable

        const int s = i % 3;
        const uint32_t aBase = uA[s] + (wm * 64 + arow) * 128;
        const uint32_t bBase = uB[s] + (wn * 32 + brow) * 128;
        const int kk = i * 32;

        #pragma unroll
        for (int ks = 0; ks < 4; ++ks) {
            uint32_t af[4][4];
            #pragma unroll
            for (int m16 = 0; m16 < 4; ++m16)
                LDSM4(af[m16][0], af[m16][1], af[m16][2], af[m16][3],
                      aBase + m16 * 2048 + ((ks * 32 + acol) ^ lxor));

            uint32_t bf[2][4];
            #pragma unroll
            for (int pr = 0; pr < 2; ++pr)
                LDSM4(bf[pr][0], bf[pr][1], bf[pr][2], bf[pr][3],
                      bBase + pr * 2048 + ((ks * 32 + bcol) ^ lxor));

            // k^2 on B fragments + rna round (only non-MMA math in the loop)
            const float kw0 = kwsm[kk + ks * 8 + (lane & 3)];
            const float kw1 = kwsm[kk + ks * 8 + 4 + (lane & 3)];
            #pragma unroll
            for (int pr = 0; pr < 2; ++pr) {
                bf[pr][0] = tf32r(__uint_as_float(bf[pr][0]) * kw0);
                bf[pr][1] = tf32r(__uint_as_float(bf[pr][1]) * kw1);
                bf[pr][2] = tf32r(__uint_as_float(bf[pr][2]) * kw0);
                bf[pr][3] = tf32r(__uint_as_float(bf[pr][3]) * kw1);
            }

            #pragma unroll
            for (int m16 = 0; m16 < 4; ++m16)
                #pragma unroll
                for (int j = 0; j < 4; ++j)
                    MMA_TF32(acc[m16][j], af[m16],
                             bf[j >> 1][(j & 1) * 2], bf[j >> 1][(j & 1) * 2 + 1]);
        }

        if (i + 2 < 8) stage(i + 2);
    }

    // ---- epilogue: scale by n2inv, row max, cross-warp combine ----
    #pragma unroll
    for (int i = 0; i < 4; ++i) {
        float v0 = NEG_INF, v1 = NEG_INF;
        #pragma unroll
        for (int j = 0; j < 4; ++j) {
            const int nb = wn * 32 + (j >> 1) * 16 + (j & 1) * 8 + 2 * (lane & 3);
            const float sc0 = n2sm[nb], sc1 = n2sm[nb + 1];
            v0 = fmaxf(v0, fmaxf(acc[i][j][0] * sc0, acc[i][j][1] * sc1));
            v1 = fmaxf(v1, fmaxf(acc[i][j][2] * sc0, acc[i][j][3] * sc1));
        }
        v0 = fmaxf(v0, __shfl_xor_sync(0xffffffffu, v0, 1));
        v0 = fmaxf(v0, __shfl_xor_sync(0xffffffffu, v0, 2));
        v1 = fmaxf(v1, __shfl_xor_sync(0xffffffffu, v1, 1));
        v1 = fmaxf(v1, __shfl_xor_sync(0xffffffffu, v1, 2));
        if ((lane & 3) == 0) {
            const int row = wm * 64 + i * 16 + (lane >> 2);
            part[wn * 128 + row]     = fmaxf(part[wn * 128 + row], v0);
            part[wn * 128 + row + 8] = fmaxf(part[wn * 128 + row + 8], v1);
        }
    }

    __syncthreads();
    if (t < 128) {
        const float v = fmaxf(fmaxf(part[t], part[128 + t]),
                              fmaxf(part[256 + t], part[384 + t]));
        g_part[mh][(size_t)(b * NL + l0 + t) * NP + p] = v;
    }
}

// ---------------------------------------------------------------------------
// Kernel 3: combine m-half partial maxima and apply n1inv
// ---------------------------------------------------------------------------
__global__ void __launch_bounds__(256) finalize_kernel(float* __restrict__ out)
{
    const int i = blockIdx.x * 256 + threadIdx.x;   // 0 .. 81919
    out[i] = g_n1inv[i] * fmaxf(g_part[0][i], g_part[1][i]);
}

// ---------------------------------------------------------------------------
extern "C" void kernel_launch(void* const* d_in, const int* in_sizes, int n_in,
                              void* d_out, int out_size)
{
    const float* s1   = (const float*)d_in[0];  // [16,256,256]
    const float* s2   = (const float*)d_in[1];  // [16,256,256]
    const float* kern = (const float*)d_in[2];  // [20,256]
    float* out = (float*)d_out;                 // [16,256,20]

    (void)in_sizes; (void)n_in; (void)out_size;

    cudaFuncSetAttribute(mpm_mma_kernel,
                         cudaFuncAttributeMaxDynamicSharedMemorySize, SMEM_DYN);

    // norms: 8192 rows x 8 threads/row, 16 rows per 128-thread block
    norms_kernel<<<512, 128>>>(s1, s2, kern);

    dim3 grid(4, NP, NB);   // (l-tile x m-half, P, B) = 1280 CTAs
    mpm_mma_kernel<<<grid, 256, SMEM_DYN>>>(s2, kern);

    finalize_kernel<<<(NB * NL * NP) / 256, 256>>>(out);
}